// round 4
// baseline (speedup 1.0000x reference)
#include <cuda_runtime.h>
#include <cuda_bf16.h>

#define N_NODES 50000
#define N_EDGES 800000
#define D_IN    128
#define D_SH    16
#define D_OUT   128
#define N_PATHS 64

// ---- static scratch (no allocations allowed) ----
__device__ int   d_cnt[N_NODES];            // per-node edge counts (histogram)
__device__ int   d_start[N_NODES + 1];      // CSR row offsets
__device__ int   d_cursor[N_NODES];         // scatter cursors
__device__ int2  d_edges[N_EDGES];          // CSR payload: {src, e}
__device__ float d_Xk[N_NODES * N_PATHS];   // Xk[n,p] = coeff[p] * x[n, ki[p]]

__global__ void zero_cnt_kernel() {
    int i = blockIdx.x * blockDim.x + threadIdx.x;
    if (i < N_NODES) d_cnt[i] = 0;
}

__global__ void hist_kernel(const int* __restrict__ dst) {
    int e = blockIdx.x * blockDim.x + threadIdx.x;
    if (e < N_EDGES) atomicAdd(&d_cnt[dst[e]], 1);
}

// Single-block exclusive scan over 50000 counts.
__global__ void scan_kernel() {
    __shared__ int sums[1024];
    int t = threadIdx.x;
    const int CH = (N_NODES + 1023) / 1024;   // 49
    int b = t * CH;
    int e = min(b + CH, N_NODES);
    int s = 0;
    for (int i = b; i < e; i++) s += d_cnt[i];
    sums[t] = s;
    __syncthreads();
    // Hillis-Steele inclusive scan
    for (int off = 1; off < 1024; off <<= 1) {
        int v = (t >= off) ? sums[t - off] : 0;
        __syncthreads();
        sums[t] += v;
        __syncthreads();
    }
    int run = (t == 0) ? 0 : sums[t - 1];     // exclusive prefix for this chunk
    for (int i = b; i < e; i++) {
        int c = d_cnt[i];
        d_start[i]  = run;
        d_cursor[i] = run;
        run += c;
    }
    if (t == 1023) d_start[N_NODES] = sums[1023];
}

__global__ void scatter_kernel(const int* __restrict__ src,
                               const int* __restrict__ dst) {
    int e = blockIdx.x * blockDim.x + threadIdx.x;
    if (e < N_EDGES) {
        int d = dst[e];
        int pos = atomicAdd(&d_cursor[d], 1);
        d_edges[pos] = make_int2(src[e], e);
    }
}

// Xk[n*64 + p] = coeff[p] * x[n*128 + ki[p]]
__global__ void xk_kernel(const float* __restrict__ x,
                          const float* __restrict__ coeff,
                          const int* __restrict__ ki) {
    int i = blockIdx.x * blockDim.x + threadIdx.x;
    if (i < N_NODES * N_PATHS) {
        int p = i & (N_PATHS - 1);
        int n = i >> 6;
        d_Xk[i] = coeff[p] * __ldg(&x[n * D_IN + ki[p]]);
    }
}

// One warp per destination node. Lane l owns paths 2l and 2l+1.
__global__ void __launch_bounds__(256)
spmm_kernel(const float* __restrict__ sh,
            const int* __restrict__ kj, const int* __restrict__ ko,
            float* __restrict__ out) {
    __shared__ float buf[8][D_OUT];
    int l = threadIdx.x & 31;
    int w = threadIdx.x >> 5;
    int node = blockIdx.x * 8 + w;
    if (node >= N_NODES) return;

    int p0 = 2 * l, p1 = 2 * l + 1;
    int kj0 = __ldg(&kj[p0]), kj1 = __ldg(&kj[p1]);
    int ko0 = __ldg(&ko[p0]), ko1 = __ldg(&ko[p1]);

    float* bf = buf[w];
    bf[l] = 0.f; bf[l + 32] = 0.f; bf[l + 64] = 0.f; bf[l + 96] = 0.f;
    __syncwarp();

    float acc0 = 0.f, acc1 = 0.f;
    int beg = d_start[node];
    int end = d_start[node + 1];
    const float2* __restrict__ Xk2 = (const float2*)d_Xk;
    const int shlane = l & 15;

    int i = beg;
    // 2-wide manual unroll: batch loads before dependent shuffles/FMAs for MLP
    for (; i + 1 < end; i += 2) {
        int2 ea = d_edges[i];
        int2 eb = d_edges[i + 1];
        float2 xa = Xk2[(size_t)ea.x * 32 + l];
        float2 xb = Xk2[(size_t)eb.x * 32 + l];
        float sa = __ldg(sh + (size_t)ea.y * D_SH + shlane);
        float sb = __ldg(sh + (size_t)eb.y * D_SH + shlane);
        float sa0 = __shfl_sync(0xffffffffu, sa, kj0);
        float sa1 = __shfl_sync(0xffffffffu, sa, kj1);
        float sb0 = __shfl_sync(0xffffffffu, sb, kj0);
        float sb1 = __shfl_sync(0xffffffffu, sb, kj1);
        acc0 = fmaf(sa0, xa.x, acc0);
        acc1 = fmaf(sa1, xa.y, acc1);
        acc0 = fmaf(sb0, xb.x, acc0);
        acc1 = fmaf(sb1, xb.y, acc1);
    }
    if (i < end) {
        int2 ea = d_edges[i];
        float2 xa = Xk2[(size_t)ea.x * 32 + l];
        float sa = __ldg(sh + (size_t)ea.y * D_SH + shlane);
        float sa0 = __shfl_sync(0xffffffffu, sa, kj0);
        float sa1 = __shfl_sync(0xffffffffu, sa, kj1);
        acc0 = fmaf(sa0, xa.x, acc0);
        acc1 = fmaf(sa1, xa.y, acc1);
    }

    atomicAdd(bf + ko0, acc0);
    atomicAdd(bf + ko1, acc1);
    __syncwarp();

    size_t o = (size_t)node * D_OUT;
    out[o + l]      = bf[l];
    out[o + l + 32] = bf[l + 32];
    out[o + l + 64] = bf[l + 64];
    out[o + l + 96] = bf[l + 96];
}

extern "C" void kernel_launch(void* const* d_in, const int* in_sizes, int n_in,
                              void* d_out, int out_size) {
    const float* x     = (const float*)d_in[0];
    const float* sh    = (const float*)d_in[1];
    const float* coeff = (const float*)d_in[2];
    const int*   src   = (const int*)d_in[3];
    const int*   dst   = (const int*)d_in[4];
    const int*   ki    = (const int*)d_in[5];
    const int*   kj    = (const int*)d_in[6];
    const int*   ko    = (const int*)d_in[7];
    float* out = (float*)d_out;

    zero_cnt_kernel<<<(N_NODES + 255) / 256, 256>>>();
    hist_kernel<<<(N_EDGES + 255) / 256, 256>>>(dst);
    scan_kernel<<<1, 1024>>>();
    scatter_kernel<<<(N_EDGES + 255) / 256, 256>>>(src, dst);
    xk_kernel<<<(N_NODES * N_PATHS + 255) / 256, 256>>>(x, coeff, ki);
    spmm_kernel<<<(N_NODES + 7) / 8, 256>>>(sh, kj, ko, out);
}

// round 7
// speedup vs baseline: 1.7373x; 1.7373x over previous
#include <cuda_runtime.h>
#include <cuda_bf16.h>

#define N_NODES 50000
#define N_EDGES 800000
#define D_IN    128
#define D_SH    16
#define D_OUT   128
#define N_PATHS 64
#define SCAN_NB ((N_NODES + 255) / 256)   // 196 blocks

// ---- static scratch (no allocations allowed) ----
__device__ int   d_cnt[N_NODES];            // per-node edge counts (histogram)
__device__ int   d_start[N_NODES + 1];      // CSR row offsets
__device__ int   d_cursor[N_NODES];         // scatter cursors
__device__ int   d_local[N_NODES];          // block-local exclusive prefix
__device__ int   d_bsum[SCAN_NB];           // per-block sums
__device__ int   d_boff[SCAN_NB];           // per-block exclusive offsets
__device__ int2  d_edges[N_EDGES];          // CSR payload: {src, e}
__device__ float d_Xk[N_NODES * N_PATHS];   // Xk[n,p] = coeff[p] * x[n, ki[p]]

__global__ void zero_cnt_kernel() {
    int i = blockIdx.x * blockDim.x + threadIdx.x;
    if (i < N_NODES) d_cnt[i] = 0;
}

__global__ void hist_kernel(const int* __restrict__ dst) {
    int e = blockIdx.x * blockDim.x + threadIdx.x;
    if (e < N_EDGES) atomicAdd(&d_cnt[dst[e]], 1);
}

// ---- 3-phase parallel exclusive scan (all coalesced) ----
__device__ __forceinline__ int block_scan_excl_256(int v, int t, int& total) {
    // inclusive warp scan
    int lane = t & 31, wid = t >> 5;
    int s = v;
    #pragma unroll
    for (int off = 1; off < 32; off <<= 1) {
        int u = __shfl_up_sync(0xffffffffu, s, off);
        if (lane >= off) s += u;
    }
    __shared__ int wsum[8];
    if (lane == 31) wsum[wid] = s;
    __syncthreads();
    if (wid == 0) {
        int ws = (lane < 8) ? wsum[lane] : 0;
        #pragma unroll
        for (int off = 1; off < 8; off <<= 1) {
            int u = __shfl_up_sync(0xffffffffu, ws, off);
            if (lane >= off) ws += u;
        }
        if (lane < 8) wsum[lane] = ws;
    }
    __syncthreads();
    int incl = s + (wid > 0 ? wsum[wid - 1] : 0);
    total = wsum[7];
    return incl - v;
}

__global__ void scan1_kernel() {
    int t = threadIdx.x;
    int i = blockIdx.x * 256 + t;
    int v = (i < N_NODES) ? d_cnt[i] : 0;
    int total;
    int excl = block_scan_excl_256(v, t, total);
    if (i < N_NODES) d_local[i] = excl;
    if (t == 0) d_bsum[blockIdx.x] = total;
}

__global__ void scan2_kernel() {
    int t = threadIdx.x;
    int v = (t < SCAN_NB) ? d_bsum[t] : 0;
    int total;
    int excl = block_scan_excl_256(v, t, total);
    if (t < SCAN_NB) d_boff[t] = excl;
}

__global__ void scan3_kernel() {
    int i = blockIdx.x * blockDim.x + threadIdx.x;
    if (i < N_NODES) {
        int s = d_local[i] + d_boff[i >> 8];
        d_start[i]  = s;
        d_cursor[i] = s;
    }
    if (i == 0) d_start[N_NODES] = N_EDGES;   // every edge counted
}

__global__ void scatter_kernel(const int* __restrict__ src,
                               const int* __restrict__ dst) {
    int e = blockIdx.x * blockDim.x + threadIdx.x;
    if (e < N_EDGES) {
        int d = dst[e];
        int pos = atomicAdd(&d_cursor[d], 1);
        d_edges[pos] = make_int2(src[e], e);
    }
}

// Xk[n*64 + p] = coeff[p] * x[n*128 + ki[p]]
__global__ void xk_kernel(const float* __restrict__ x,
                          const float* __restrict__ coeff,
                          const int* __restrict__ ki) {
    int i = blockIdx.x * blockDim.x + threadIdx.x;
    if (i < N_NODES * N_PATHS) {
        int p = i & (N_PATHS - 1);
        int n = i >> 6;
        d_Xk[i] = coeff[p] * __ldg(&x[n * D_IN + ki[p]]);
    }
}

// One warp per destination node. Lane l owns paths 2l and 2l+1.
__global__ void __launch_bounds__(256)
spmm_kernel(const float* __restrict__ sh,
            const int* __restrict__ kj, const int* __restrict__ ko,
            float* __restrict__ out) {
    __shared__ float buf[8][D_OUT];
    int l = threadIdx.x & 31;
    int w = threadIdx.x >> 5;
    int node = blockIdx.x * 8 + w;
    if (node >= N_NODES) return;

    int p0 = 2 * l, p1 = 2 * l + 1;
    int kj0 = __ldg(&kj[p0]), kj1 = __ldg(&kj[p1]);
    int ko0 = __ldg(&ko[p0]), ko1 = __ldg(&ko[p1]);

    float* bf = buf[w];
    bf[l] = 0.f; bf[l + 32] = 0.f; bf[l + 64] = 0.f; bf[l + 96] = 0.f;
    __syncwarp();

    float acc0 = 0.f, acc1 = 0.f;
    int beg = d_start[node];
    int end = d_start[node + 1];
    const float2* __restrict__ Xk2 = (const float2*)d_Xk;
    const int shlane = l & 15;

    int i = beg;
    // 2-wide manual unroll: batch loads before dependent shuffles/FMAs for MLP
    for (; i + 1 < end; i += 2) {
        int2 ea = d_edges[i];
        int2 eb = d_edges[i + 1];
        float2 xa = Xk2[(size_t)ea.x * 32 + l];
        float2 xb = Xk2[(size_t)eb.x * 32 + l];
        float sa = __ldg(sh + (size_t)ea.y * D_SH + shlane);
        float sb = __ldg(sh + (size_t)eb.y * D_SH + shlane);
        float sa0 = __shfl_sync(0xffffffffu, sa, kj0);
        float sa1 = __shfl_sync(0xffffffffu, sa, kj1);
        float sb0 = __shfl_sync(0xffffffffu, sb, kj0);
        float sb1 = __shfl_sync(0xffffffffu, sb, kj1);
        acc0 = fmaf(sa0, xa.x, acc0);
        acc1 = fmaf(sa1, xa.y, acc1);
        acc0 = fmaf(sb0, xb.x, acc0);
        acc1 = fmaf(sb1, xb.y, acc1);
    }
    if (i < end) {
        int2 ea = d_edges[i];
        float2 xa = Xk2[(size_t)ea.x * 32 + l];
        float sa = __ldg(sh + (size_t)ea.y * D_SH + shlane);
        float sa0 = __shfl_sync(0xffffffffu, sa, kj0);
        float sa1 = __shfl_sync(0xffffffffu, sa, kj1);
        acc0 = fmaf(sa0, xa.x, acc0);
        acc1 = fmaf(sa1, xa.y, acc1);
    }

    atomicAdd(bf + ko0, acc0);
    atomicAdd(bf + ko1, acc1);
    __syncwarp();

    size_t o = (size_t)node * D_OUT;
    out[o + l]      = bf[l];
    out[o + l + 32] = bf[l + 32];
    out[o + l + 64] = bf[l + 64];
    out[o + l + 96] = bf[l + 96];
}

extern "C" void kernel_launch(void* const* d_in, const int* in_sizes, int n_in,
                              void* d_out, int out_size) {
    const float* x     = (const float*)d_in[0];
    const float* sh    = (const float*)d_in[1];
    const float* coeff = (const float*)d_in[2];
    const int*   src   = (const int*)d_in[3];
    const int*   dst   = (const int*)d_in[4];
    const int*   ki    = (const int*)d_in[5];
    const int*   kj    = (const int*)d_in[6];
    const int*   ko    = (const int*)d_in[7];
    float* out = (float*)d_out;

    zero_cnt_kernel<<<(N_NODES + 255) / 256, 256>>>();
    hist_kernel<<<(N_EDGES + 255) / 256, 256>>>(dst);
    scan1_kernel<<<SCAN_NB, 256>>>();
    scan2_kernel<<<1, 256>>>();
    scan3_kernel<<<(N_NODES + 255) / 256, 256>>>();
    scatter_kernel<<<(N_EDGES + 255) / 256, 256>>>(src, dst);
    xk_kernel<<<(N_NODES * N_PATHS + 255) / 256, 256>>>(x, coeff, ki);
    spmm_kernel<<<(N_NODES + 7) / 8, 256>>>(sh, kj, ko, out);
}

// round 8
// speedup vs baseline: 2.1974x; 1.2648x over previous
#include <cuda_runtime.h>
#include <cuda_bf16.h>

#define N_NODES 50000
#define N_EDGES 800000
#define D_IN    128
#define D_SH    16
#define D_OUT   128
#define N_PATHS 64
#define SCAN_NB ((N_NODES + 255) / 256)      // 196
#define HIST_NB ((N_EDGES + 255) / 256)      // 3125
#define XK_NB   ((N_NODES * N_PATHS + 255) / 256)  // 12500

// ---- static scratch (no allocations allowed) ----
// INVARIANT: d_cnt is all-zero at kernel_launch entry. Zero-initialized at
// module load; scanA re-zeroes it after consuming, so every graph replay
// re-establishes the invariant for the next one.
__device__ int   d_cnt[N_NODES];
__device__ int   d_start[N_NODES + 1];
__device__ int   d_cursor[N_NODES];
__device__ int   d_local[N_NODES];          // block-local exclusive prefix
__device__ int   d_bsum[SCAN_NB];           // per-block sums
__device__ int2  d_edges[N_EDGES];          // CSR payload: {src, e}
__device__ float d_Xk[N_NODES * N_PATHS];   // Xk[n,p] = coeff[p] * x[n, ki[p]]

// ---- fused histogram + Xk precompute (independent jobs, one grid) ----
__global__ void __launch_bounds__(256)
hist_xk_kernel(const int* __restrict__ dst,
               const float* __restrict__ x,
               const float* __restrict__ coeff,
               const int* __restrict__ ki) {
    int b = blockIdx.x;
    if (b < HIST_NB) {
        int e = b * 256 + threadIdx.x;
        if (e < N_EDGES) atomicAdd(&d_cnt[dst[e]], 1);   // no return use -> REDG
    } else {
        int i = (b - HIST_NB) * 256 + threadIdx.x;
        if (i < N_NODES * N_PATHS) {
            int p = i & (N_PATHS - 1);
            int n = i >> 6;
            d_Xk[i] = coeff[p] * __ldg(&x[n * D_IN + ki[p]]);
        }
    }
}

// ---- scanA: block-local exclusive scan of d_cnt; zero d_cnt after read ----
__device__ __forceinline__ int block_scan_excl_256(int v, int t, int& total) {
    int lane = t & 31, wid = t >> 5;
    int s = v;
    #pragma unroll
    for (int off = 1; off < 32; off <<= 1) {
        int u = __shfl_up_sync(0xffffffffu, s, off);
        if (lane >= off) s += u;
    }
    __shared__ int wsum[8];
    if (lane == 31) wsum[wid] = s;
    __syncthreads();
    if (wid == 0) {
        int ws = (lane < 8) ? wsum[lane] : 0;
        #pragma unroll
        for (int off = 1; off < 8; off <<= 1) {
            int u = __shfl_up_sync(0xffffffffu, ws, off);
            if (lane >= off) ws += u;
        }
        if (lane < 8) wsum[lane] = ws;
    }
    __syncthreads();
    int incl = s + (wid > 0 ? wsum[wid - 1] : 0);
    total = wsum[7];
    return incl - v;
}

__global__ void __launch_bounds__(256) scanA_kernel() {
    int t = threadIdx.x;
    int i = blockIdx.x * 256 + t;
    int v = 0;
    if (i < N_NODES) {
        v = d_cnt[i];
        d_cnt[i] = 0;                         // re-establish invariant
    }
    int total;
    int excl = block_scan_excl_256(v, t, total);
    if (i < N_NODES) d_local[i] = excl;
    if (t == 0) d_bsum[blockIdx.x] = total;
}

// ---- scanB: each block redundantly computes its own offset from bsum ----
__global__ void __launch_bounds__(256) scanB_kernel() {
    __shared__ int red[8];
    __shared__ int blk_off;
    int t = threadIdx.x;
    int b = blockIdx.x;
    int lane = t & 31, wid = t >> 5;

    int v = (t < b) ? d_bsum[t] : 0;          // b <= 195 < 256
    #pragma unroll
    for (int off = 16; off > 0; off >>= 1)
        v += __shfl_down_sync(0xffffffffu, v, off);
    if (lane == 0) red[wid] = v;
    __syncthreads();
    if (t == 0) {
        int s = 0;
        #pragma unroll
        for (int k = 0; k < 8; k++) s += red[k];
        blk_off = s;
    }
    __syncthreads();

    int i = b * 256 + t;
    if (i < N_NODES) {
        int s = d_local[i] + blk_off;
        d_start[i]  = s;
        d_cursor[i] = s;
    }
    if (b == 0 && t == 0) d_start[N_NODES] = N_EDGES;
}

__global__ void __launch_bounds__(256)
scatter_kernel(const int* __restrict__ src,
               const int* __restrict__ dst) {
    int e = blockIdx.x * blockDim.x + threadIdx.x;
    if (e < N_EDGES) {
        int d = dst[e];
        int pos = atomicAdd(&d_cursor[d], 1);
        d_edges[pos] = make_int2(src[e], e);
    }
}

// One warp per destination node. Lane l owns paths 2l and 2l+1.
// Edge descriptors are loaded coalesced (lane l takes edge base+l) and
// broadcast via shfl, instead of per-iteration uniform LDGs.
__global__ void __launch_bounds__(256)
spmm_kernel(const float* __restrict__ sh,
            const int* __restrict__ kj, const int* __restrict__ ko,
            float* __restrict__ out) {
    __shared__ float buf[8][D_OUT];
    const unsigned FULL = 0xffffffffu;
    int l = threadIdx.x & 31;
    int w = threadIdx.x >> 5;
    int node = blockIdx.x * 8 + w;
    if (node >= N_NODES) return;

    int p0 = 2 * l, p1 = 2 * l + 1;
    int kj0 = __ldg(&kj[p0]), kj1 = __ldg(&kj[p1]);
    int ko0 = __ldg(&ko[p0]), ko1 = __ldg(&ko[p1]);

    float* bf = buf[w];
    bf[l] = 0.f; bf[l + 32] = 0.f; bf[l + 64] = 0.f; bf[l + 96] = 0.f;
    __syncwarp();

    float acc0 = 0.f, acc1 = 0.f;
    int beg = d_start[node];
    int end = d_start[node + 1];
    const float2* __restrict__ Xk2 = (const float2*)d_Xk;
    const int shlane = l & 15;

    for (int base = beg; base < end; base += 32) {
        int n = end - base;
        if (n > 32) n = 32;
        int2 ed = make_int2(0, 0);
        if (base + l < end) ed = d_edges[base + l];   // coalesced

        int j = 0;
        for (; j + 1 < n; j += 2) {
            int na = __shfl_sync(FULL, ed.x, j);
            int ea = __shfl_sync(FULL, ed.y, j);
            int nb = __shfl_sync(FULL, ed.x, j + 1);
            int eb = __shfl_sync(FULL, ed.y, j + 1);
            float2 xa = Xk2[(size_t)na * 32 + l];
            float2 xb = Xk2[(size_t)nb * 32 + l];
            float sa = __ldg(sh + (size_t)ea * D_SH + shlane);
            float sb = __ldg(sh + (size_t)eb * D_SH + shlane);
            float sa0 = __shfl_sync(FULL, sa, kj0);
            float sa1 = __shfl_sync(FULL, sa, kj1);
            float sb0 = __shfl_sync(FULL, sb, kj0);
            float sb1 = __shfl_sync(FULL, sb, kj1);
            acc0 = fmaf(sa0, xa.x, acc0);
            acc1 = fmaf(sa1, xa.y, acc1);
            acc0 = fmaf(sb0, xb.x, acc0);
            acc1 = fmaf(sb1, xb.y, acc1);
        }
        if (j < n) {
            int na = __shfl_sync(FULL, ed.x, j);
            int ea = __shfl_sync(FULL, ed.y, j);
            float2 xa = Xk2[(size_t)na * 32 + l];
            float sa = __ldg(sh + (size_t)ea * D_SH + shlane);
            float sa0 = __shfl_sync(FULL, sa, kj0);
            float sa1 = __shfl_sync(FULL, sa, kj1);
            acc0 = fmaf(sa0, xa.x, acc0);
            acc1 = fmaf(sa1, xa.y, acc1);
        }
    }

    atomicAdd(bf + ko0, acc0);
    atomicAdd(bf + ko1, acc1);
    __syncwarp();

    size_t o = (size_t)node * D_OUT;
    out[o + l]      = bf[l];
    out[o + l + 32] = bf[l + 32];
    out[o + l + 64] = bf[l + 64];
    out[o + l + 96] = bf[l + 96];
}

extern "C" void kernel_launch(void* const* d_in, const int* in_sizes, int n_in,
                              void* d_out, int out_size) {
    const float* x     = (const float*)d_in[0];
    const float* sh    = (const float*)d_in[1];
    const float* coeff = (const float*)d_in[2];
    const int*   src   = (const int*)d_in[3];
    const int*   dst   = (const int*)d_in[4];
    const int*   ki    = (const int*)d_in[5];
    const int*   kj    = (const int*)d_in[6];
    const int*   ko    = (const int*)d_in[7];
    float* out = (float*)d_out;

    hist_xk_kernel<<<HIST_NB + XK_NB, 256>>>(dst, x, coeff, ki);
    scanA_kernel<<<SCAN_NB, 256>>>();
    scanB_kernel<<<SCAN_NB, 256>>>();
    scatter_kernel<<<HIST_NB, 256>>>(src, dst);
    spmm_kernel<<<(N_NODES + 7) / 8, 256>>>(sh, kj, ko, out);
}

// round 10
// speedup vs baseline: 2.3972x; 1.0909x over previous
#include <cuda_runtime.h>
#include <cuda_fp16.h>

#define N_NODES 50000
#define N_EDGES 800000
#define D_IN    128
#define D_SH    16
#define D_OUT   128
#define N_PATHS 64
#define SCAN_NB ((N_NODES + 255) / 256)              // 196
#define HIST_NB ((N_EDGES + 255) / 256)              // 3125
#define XK_NB   ((N_NODES * 32 + 255) / 256)         // 6250 (half2 pairs)

// ---- static scratch (no allocations allowed) ----
// INVARIANTS at kernel_launch entry (zero-init at load, re-established each run):
//   d_cnt all zero (scan kernel zeroes after read)
//   d_total == 0   (scatter thread 0 resets it)
__device__ int     d_cnt[N_NODES];
__device__ int     d_start[N_NODES];        // segment begin (permuted placement)
__device__ int     d_stop[N_NODES];         // segment end
__device__ int     d_cursor[N_NODES];
__device__ int     d_total;                 // ticket counter for segment placement
__device__ int2    d_edges[N_EDGES];        // CSR payload: {src, e}
__device__ __half2 d_XkH[N_NODES * 32];     // XkH[n,q] = (coeff[2q]*x[n,ki[2q]], coeff[2q+1]*x[n,ki[2q+1]])

// ---- fused histogram + Xk(half2) precompute (independent jobs, one grid) ----
__global__ void __launch_bounds__(256)
hist_xk_kernel(const int* __restrict__ dst,
               const float* __restrict__ x,
               const float* __restrict__ coeff,
               const int* __restrict__ ki) {
    int b = blockIdx.x;
    if (b < HIST_NB) {
        int e = b * 256 + threadIdx.x;
        if (e < N_EDGES) atomicAdd(&d_cnt[dst[e]], 1);
    } else {
        int i = (b - HIST_NB) * 256 + threadIdx.x;
        if (i < N_NODES * 32) {
            int n = i >> 5;
            int q = i & 31;
            int ki0 = __ldg(&ki[2 * q]),     ki1 = __ldg(&ki[2 * q + 1]);
            float c0 = __ldg(&coeff[2 * q]), c1 = __ldg(&coeff[2 * q + 1]);
            float f0 = c0 * __ldg(&x[n * D_IN + ki0]);
            float f1 = c1 * __ldg(&x[n * D_IN + ki1]);
            d_XkH[i] = __floats2half2_rn(f0, f1);
        }
    }
}

// ---- single-pass scan: block-local exclusive scan + atomic ticket offset ----
// Segment placement across blocks is arbitrary (disjointness is all that
// correctness needs), so no ordered global prefix is required.
__global__ void __launch_bounds__(256) scan_kernel() {
    __shared__ int wsum[8];
    __shared__ int blk_off;
    int t = threadIdx.x;
    int lane = t & 31, wid = t >> 5;
    int i = blockIdx.x * 256 + t;

    int v = 0;
    if (i < N_NODES) {
        v = d_cnt[i];
        d_cnt[i] = 0;                        // re-establish invariant
    }
    // inclusive warp scan
    int s = v;
    #pragma unroll
    for (int off = 1; off < 32; off <<= 1) {
        int u = __shfl_up_sync(0xffffffffu, s, off);
        if (lane >= off) s += u;
    }
    if (lane == 31) wsum[wid] = s;
    __syncthreads();
    if (wid == 0) {
        int ws = (lane < 8) ? wsum[lane] : 0;
        #pragma unroll
        for (int off = 1; off < 8; off <<= 1) {
            int u = __shfl_up_sync(0xffffffffu, ws, off);
            if (lane >= off) ws += u;
        }
        if (lane < 8) wsum[lane] = ws;
    }
    __syncthreads();
    int incl = s + (wid > 0 ? wsum[wid - 1] : 0);
    if (t == 0) blk_off = atomicAdd(&d_total, wsum[7]);
    __syncthreads();

    if (i < N_NODES) {
        int b0 = blk_off + incl - v;
        d_start[i]  = b0;
        d_stop[i]   = b0 + v;
        d_cursor[i] = b0;
    }
}

__global__ void __launch_bounds__(256)
scatter_kernel(const int* __restrict__ src,
               const int* __restrict__ dst) {
    int e = blockIdx.x * blockDim.x + threadIdx.x;
    if (e == 0) d_total = 0;                 // reset ticket for next replay
    if (e < N_EDGES) {
        int d = dst[e];
        int pos = atomicAdd(&d_cursor[d], 1);
        d_edges[pos] = make_int2(src[e], e);
    }
}

// One warp per destination node. Lane l owns paths 2l and 2l+1.
// Edge descriptors loaded coalesced + shfl-broadcast; Xk in half2 (128B/edge).
__global__ void __launch_bounds__(256)
spmm_kernel(const float* __restrict__ sh,
            const int* __restrict__ kj, const int* __restrict__ ko,
            float* __restrict__ out) {
    __shared__ float buf[8][D_OUT];
    const unsigned FULL = 0xffffffffu;
    int l = threadIdx.x & 31;
    int w = threadIdx.x >> 5;
    int node = blockIdx.x * 8 + w;
    if (node >= N_NODES) return;

    int p0 = 2 * l, p1 = 2 * l + 1;
    int kj0 = __ldg(&kj[p0]), kj1 = __ldg(&kj[p1]);
    int ko0 = __ldg(&ko[p0]), ko1 = __ldg(&ko[p1]);

    float* bf = buf[w];
    bf[l] = 0.f; bf[l + 32] = 0.f; bf[l + 64] = 0.f; bf[l + 96] = 0.f;
    __syncwarp();

    float acc0 = 0.f, acc1 = 0.f;
    int beg = d_start[node];
    int end = d_stop[node];
    const int shlane = l & 15;

    for (int base = beg; base < end; base += 32) {
        int n = end - base;
        if (n > 32) n = 32;
        int2 ed = make_int2(0, 0);
        if (base + l < end) ed = d_edges[base + l];   // coalesced

        int j = 0;
        for (; j + 1 < n; j += 2) {
            int na = __shfl_sync(FULL, ed.x, j);
            int ea = __shfl_sync(FULL, ed.y, j);
            int nb = __shfl_sync(FULL, ed.x, j + 1);
            int eb = __shfl_sync(FULL, ed.y, j + 1);
            __half2 ha = d_XkH[(size_t)na * 32 + l];
            __half2 hb = d_XkH[(size_t)nb * 32 + l];
            float sa = __ldg(sh + (size_t)ea * D_SH + shlane);
            float sb = __ldg(sh + (size_t)eb * D_SH + shlane);
            float sa0 = __shfl_sync(FULL, sa, kj0);
            float sa1 = __shfl_sync(FULL, sa, kj1);
            float sb0 = __shfl_sync(FULL, sb, kj0);
            float sb1 = __shfl_sync(FULL, sb, kj1);
            float2 xa = __half22float2(ha);
            float2 xb = __half22float2(hb);
            acc0 = fmaf(sa0, xa.x, acc0);
            acc1 = fmaf(sa1, xa.y, acc1);
            acc0 = fmaf(sb0, xb.x, acc0);
            acc1 = fmaf(sb1, xb.y, acc1);
        }
        if (j < n) {
            int na = __shfl_sync(FULL, ed.x, j);
            int ea = __shfl_sync(FULL, ed.y, j);
            __half2 ha = d_XkH[(size_t)na * 32 + l];
            float sa = __ldg(sh + (size_t)ea * D_SH + shlane);
            float sa0 = __shfl_sync(FULL, sa, kj0);
            float sa1 = __shfl_sync(FULL, sa, kj1);
            float2 xa = __half22float2(ha);
            acc0 = fmaf(sa0, xa.x, acc0);
            acc1 = fmaf(sa1, xa.y, acc1);
        }
    }

    atomicAdd(bf + ko0, acc0);
    atomicAdd(bf + ko1, acc1);
    __syncwarp();

    size_t o = (size_t)node * D_OUT;
    out[o + l]      = bf[l];
    out[o + l + 32] = bf[l + 32];
    out[o + l + 64] = bf[l + 64];
    out[o + l + 96] = bf[l + 96];
}

extern "C" void kernel_launch(void* const* d_in, const int* in_sizes, int n_in,
                              void* d_out, int out_size) {
    const float* x     = (const float*)d_in[0];
    const float* sh    = (const float*)d_in[1];
    const float* coeff = (const float*)d_in[2];
    const int*   src   = (const int*)d_in[3];
    const int*   dst   = (const int*)d_in[4];
    const int*   ki    = (const int*)d_in[5];
    const int*   kj    = (const int*)d_in[6];
    const int*   ko    = (const int*)d_in[7];
    float* out = (float*)d_out;

    hist_xk_kernel<<<HIST_NB + XK_NB, 256>>>(dst, x, coeff, ki);
    scan_kernel<<<SCAN_NB, 256>>>();
    scatter_kernel<<<HIST_NB, 256>>>(src, dst);
    spmm_kernel<<<(N_NODES + 7) / 8, 256>>>(sh, kj, ko, out);
}